// round 15
// baseline (speedup 1.0000x reference)
#include <cuda_runtime.h>
#include <cuda_fp16.h>
#include <cstdint>
#include <math.h>

// Problem constants
#define B_   8
#define T_   4096
#define H_   1024
#define NH_  16
#define HD_  64
#define MTOT (B_ * T_)          // 32768
#define SCALE 0.125f            // 1/sqrt(64)
#define WTS_SCALE 256.0f
#define WTS_INV   (1.0f / 256.0f)

// ---------------- scratch ----------------
__device__ __half g_hsh[(size_t)MTOT * H_];       // 64 MB
__device__ __half g_qh[(size_t)MTOT * H_];        // 64 MB
__device__ __half g_wqh[H_ * H_];
__device__ __half g_wts[(size_t)B_ * H_ * H_];    // 16 MB
__device__ __half g_uqh[NH_ * H_];
__device__ __half g_ukh[B_ * NH_ * H_];
__device__ float  g_ufold2[64 * NH_ * H_];        // q-fold partials [64][16][1024]
__device__ float  g_ufoldk[64 * B_ * NH_ * H_];   // k-fold partials [64][8][16][1024]
__device__ float  g_score[(size_t)B_ * NH_ * T_]; // 2 MB (raw scores)
__device__ float  g_pmax[B_ * NH_ * 64];
__device__ float  g_psum[B_ * NH_ * 64];
__device__ float  g_ph[4 * B_ * NH_ * H_];        // pooled-hs partials [4 tc][B][NH][H]
__device__ float  g_pq[B_ * H_];
__device__ float  g_sb[B_ * NH_];

// ---------------- streams/events (host objects, static init) ----------------
struct StreamPack {
    cudaStream_t side;
    cudaEvent_t evFork, evHs, evA, evJoin;
    StreamPack() {
        cudaStreamCreateWithFlags(&side, cudaStreamNonBlocking);
        cudaEventCreateWithFlags(&evFork, cudaEventDisableTiming);
        cudaEventCreateWithFlags(&evHs, cudaEventDisableTiming);
        cudaEventCreateWithFlags(&evA, cudaEventDisableTiming);
        cudaEventCreateWithFlags(&evJoin, cudaEventDisableTiming);
    }
};
static StreamPack g_sp;

// ---------------- common PTX ----------------
__device__ __forceinline__ void cp16(uint32_t smem, const void* gmem) {
    asm volatile("cp.async.cg.shared.global [%0], [%1], 16;" :: "r"(smem), "l"(gmem));
}
__device__ __forceinline__ void cp_commit() { asm volatile("cp.async.commit_group;"); }
template <int N> __device__ __forceinline__ void cp_wait() {
    asm volatile("cp.async.wait_group %0;" :: "n"(N));
}
__device__ __forceinline__ void ldsm_x4(uint32_t* r, uint32_t addr) {
    asm volatile("ldmatrix.sync.aligned.m8n8.x4.shared.b16 {%0,%1,%2,%3}, [%4];"
                 : "=r"(r[0]), "=r"(r[1]), "=r"(r[2]), "=r"(r[3]) : "r"(addr));
}
__device__ __forceinline__ void mma_f16(float* c, const uint32_t* a, const uint32_t* b) {
    asm volatile(
        "mma.sync.aligned.m16n8k16.row.col.f32.f16.f16.f32 "
        "{%0,%1,%2,%3}, {%4,%5,%6,%7}, {%8,%9}, {%0,%1,%2,%3};"
        : "+f"(c[0]), "+f"(c[1]), "+f"(c[2]), "+f"(c[3])
        : "r"(a[0]), "r"(a[1]), "r"(a[2]), "r"(a[3]),
          "r"(b[0]), "r"(b[1]));
}

// =================================================================
// fp16 GEMM: block 256x128, warp 64x64 (8 warps, 4m x 2n), BK=64, 3-stage ring
// =================================================================
#define BM 256
#define BN 128
#define BKK 64
#define ROWH 72
#define STAGES 3
#define ASTG_BYTES (BM * ROWH * 2)
#define BSTG_BYTES (BN * ROWH * 2)
#define STG_BYTES  (ASTG_BYTES + BSTG_BYTES)
#define SMEM_DYN   (STAGES * STG_BYTES)      // 165888

template <int MODE>
__global__ __launch_bounds__(256, 1)
void gemm_h(const __half* __restrict__ A,
            const __half* __restrict__ W0, const float* __restrict__ bias0,
            const __half* __restrict__ addend,
            __half* __restrict__ C0h, float* __restrict__ Cf)
{
    const int K = H_, N = H_;
    extern __shared__ __half smem[];
    const uint32_t sb = (uint32_t)__cvta_generic_to_shared(smem);

    const int tid = threadIdx.x;
    const int bm  = blockIdx.y * BM;

    const __half* W = W0; const float* bias = bias0;
    int bn = blockIdx.x * BN;
    if (MODE == 1) W = W0 + (size_t)(bm / T_) * H_ * H_;

    const int wid = tid >> 5, lane = tid & 31;
    const int warp_m = wid >> 1, warp_n = wid & 1;
    const int gid = lane >> 2, lm = lane & 3;

    const int a_r = (lane & 7) + ((lane >> 3) & 1) * 8;
    const int a_c = (lane >> 4) * 8;
    const int b_r = (lane & 7) + ((lane >> 4) & 1) * 8;
    const int b_c = ((lane >> 3) & 1) * 8;

    float acc[4][8][4];
    #pragma unroll
    for (int i = 0; i < 4; i++)
        #pragma unroll
        for (int j = 0; j < 8; j++)
            #pragma unroll
            for (int r = 0; r < 4; r++) acc[i][j][r] = 0.f;

    auto issue_copy = [&](int kt, int s) {
        const int k0 = kt * BKK;
        const uint32_t ab = sb + s * STG_BYTES;
        const uint32_t bb = ab + ASTG_BYTES;
        #pragma unroll
        for (int l = 0; l < 8; l++) {
            int c = l * 256 + tid;
            int row = c >> 3, colh = (c & 7) * 8;
            cp16(ab + (row * ROWH + colh) * 2, A + (size_t)(bm + row) * K + k0 + colh);
        }
        #pragma unroll
        for (int l = 0; l < 4; l++) {
            int c = l * 256 + tid;
            int row = c >> 3, colh = (c & 7) * 8;
            cp16(bb + (row * ROWH + colh) * 2, W + (size_t)(bn + row) * K + k0 + colh);
        }
        cp_commit();
    };

    issue_copy(0, 0);
    issue_copy(1, 1);

    const int KT = K / BKK;   // 16
    for (int kt = 0; kt < KT; kt++) {
        cp_wait<1>();
        __syncthreads();
        if (kt + 2 < KT) issue_copy(kt + 2, (kt + 2) % STAGES);

        const uint32_t ab = sb + (kt % STAGES) * STG_BYTES;
        const uint32_t bb = ab + ASTG_BYTES;

        #pragma unroll
        for (int kk = 0; kk < 4; kk++) {
            const int kb = kk * 16;
            uint32_t af[4][4], bf[8][2];
            #pragma unroll
            for (int mt = 0; mt < 4; mt++)
                ldsm_x4(af[mt],
                        ab + ((warp_m * 64 + mt * 16 + a_r) * ROWH + kb + a_c) * 2);
            #pragma unroll
            for (int ntp = 0; ntp < 4; ntp++) {
                uint32_t r4[4];
                ldsm_x4(r4,
                        bb + ((warp_n * 64 + ntp * 16 + b_r) * ROWH + kb + b_c) * 2);
                bf[ntp * 2 + 0][0] = r4[0]; bf[ntp * 2 + 0][1] = r4[1];
                bf[ntp * 2 + 1][0] = r4[2]; bf[ntp * 2 + 1][1] = r4[3];
            }
            #pragma unroll
            for (int mt = 0; mt < 4; mt++)
                #pragma unroll
                for (int nt = 0; nt < 8; nt++)
                    mma_f16(acc[mt][nt], af[mt], bf[nt]);
        }
    }

    #pragma unroll
    for (int mt = 0; mt < 4; mt++) {
        #pragma unroll
        for (int nt = 0; nt < 8; nt++) {
            int row0 = bm + warp_m * 64 + mt * 16 + gid;
            int col  = bn + warp_n * 64 + nt * 8 + lm * 2;
            float b0 = bias[col], b1 = bias[col + 1];
            #pragma unroll
            for (int hh = 0; hh < 2; hh++) {
                int row = row0 + hh * 8;
                size_t off = (size_t)row * N + col;
                if (MODE == 0) {
                    __half2 v = __floats2half2_rn(acc[mt][nt][hh * 2 + 0] + b0,
                                                  acc[mt][nt][hh * 2 + 1] + b1);
                    *(__half2*)(C0h + off) = v;
                } else {
                    __half2 ad = *(const __half2*)(addend + off);
                    float2 v;
                    v.x = acc[mt][nt][hh * 2 + 0] * WTS_INV + b0 + __low2float(ad);
                    v.y = acc[mt][nt][hh * 2 + 1] * WTS_INV + b1 + __high2float(ad);
                    *(float2*)(Cf + off) = v;
                }
            }
        }
    }
}

// =================================================================
// score GEMM + partial softmax stats
// =================================================================
#define SNC  16
#define SROW 72
#define WROW 1032
#define S_QS_STG (64 * SROW * 2)
#define S_WL     (NH_ * WROW * 2)
#define S_SMEM   (S_WL + 3 * S_QS_STG)

__global__ __launch_bounds__(128)
void score_mma(const __half* __restrict__ X, const __half* __restrict__ wl_g,
               const float* __restrict__ bl, const float* __restrict__ mask,
               float* __restrict__ score, float* __restrict__ pmax,
               float* __restrict__ psum, int wl_bstride, int bl_bstride)
{
    extern __shared__ char smemc[];
    const uint32_t sb = (uint32_t)__cvta_generic_to_shared(smemc);
    const int tid = threadIdx.x, wid = tid >> 5, lane = tid & 31;
    const int bt0 = blockIdx.x * 64;
    const int b = bt0 >> 12;
    const __half* wl = wl_g + (size_t)b * wl_bstride;
    const float* blp = bl + (size_t)b * bl_bstride;

    const int a_r = (lane & 7) + ((lane >> 3) & 1) * 8;
    const int a_c = (lane >> 4) * 8;
    const int b_r = (lane & 7) + ((lane >> 4) & 1) * 8;
    const int b_c = ((lane >> 3) & 1) * 8;

    auto issue_q = [&](int kc, int s) {
        const uint32_t qb = sb + S_WL + s * S_QS_STG;
        #pragma unroll
        for (int l = 0; l < 4; l++) {
            int c = l * 128 + tid;
            int row = c >> 3, colh = (c & 7) * 8;
            cp16(qb + (row * SROW + colh) * 2,
                 X + (size_t)(bt0 + row) * H_ + kc * 64 + colh);
        }
        cp_commit();
    };

    #pragma unroll
    for (int l = 0; l < 16; l++) {
        int c = l * 128 + tid;
        int row = c >> 7, c8 = (c & 127) * 8;
        cp16(sb + (row * WROW + c8) * 2, wl + (size_t)row * H_ + c8);
    }
    issue_q(0, 0);
    issue_q(1, 1);

    float acc[2][4];
    #pragma unroll
    for (int n = 0; n < 2; n++)
        #pragma unroll
        for (int r = 0; r < 4; r++) acc[n][r] = 0.f;

    for (int kc = 0; kc < SNC; kc++) {
        cp_wait<1>();
        __syncthreads();
        if (kc + 2 < SNC) issue_q(kc + 2, (kc + 2) % 3);

        const uint32_t qb = sb + S_WL + (kc % 3) * S_QS_STG;
        #pragma unroll
        for (int kk = 0; kk < 4; kk++) {
            const int kb = kk * 16;
            uint32_t af[4], r4[4];
            ldsm_x4(af, qb + ((wid * 16 + a_r) * SROW + kb + a_c) * 2);
            ldsm_x4(r4, sb + (b_r * WROW + kc * 64 + kb + b_c) * 2);
            uint32_t bf0[2] = { r4[0], r4[1] }, bf1[2] = { r4[2], r4[3] };
            mma_f16(acc[0], af, bf0);
            mma_f16(acc[1], af, bf1);
        }
    }

    const int gid = lane >> 2, lm = lane & 3;
    const int bt = bt0 + wid * 16 + gid;
    const int t = bt & (T_ - 1);
    const float madd0 = (1.f - mask[bt]) * -10000.f;
    const float madd8 = (1.f - mask[bt + 8]) * -10000.f;

    float sc[2][2][2];
    #pragma unroll
    for (int n = 0; n < 2; n++) {
        #pragma unroll
        for (int e = 0; e < 2; e++) {
            int h = n * 8 + lm * 2 + e;
            sc[n][e][0] = SCALE * (acc[n][e]     + blp[h]) + madd0;
            sc[n][e][1] = SCALE * (acc[n][2 + e] + blp[h]) + madd8;
            float* sp = score + ((size_t)b * NH_ + h) * T_;
            sp[t]     = sc[n][e][0];
            sp[t + 8] = sc[n][e][1];
        }
    }

    __shared__ float pmx_s[4][NH_], psm_s[4][NH_];
    float m[2][2];
    #pragma unroll
    for (int n = 0; n < 2; n++)
        #pragma unroll
        for (int e = 0; e < 2; e++) m[n][e] = fmaxf(sc[n][e][0], sc[n][e][1]);
    #pragma unroll
    for (int msk = 4; msk <= 16; msk <<= 1)
        #pragma unroll
        for (int n = 0; n < 2; n++)
            #pragma unroll
            for (int e = 0; e < 2; e++)
                m[n][e] = fmaxf(m[n][e], __shfl_xor_sync(0xffffffffu, m[n][e], msk));
    if (gid == 0)
        #pragma unroll
        for (int n = 0; n < 2; n++)
            #pragma unroll
            for (int e = 0; e < 2; e++)
                pmx_s[wid][n * 8 + lm * 2 + e] = m[n][e];
    __syncthreads();

    float s2[2][2];
    #pragma unroll
    for (int n = 0; n < 2; n++)
        #pragma unroll
        for (int e = 0; e < 2; e++) {
            int h = n * 8 + lm * 2 + e;
            float g = fmaxf(fmaxf(pmx_s[0][h], pmx_s[1][h]),
                            fmaxf(pmx_s[2][h], pmx_s[3][h]));
            s2[n][e] = __expf(sc[n][e][0] - g) + __expf(sc[n][e][1] - g);
        }
    #pragma unroll
    for (int msk = 4; msk <= 16; msk <<= 1)
        #pragma unroll
        for (int n = 0; n < 2; n++)
            #pragma unroll
            for (int e = 0; e < 2; e++)
                s2[n][e] += __shfl_xor_sync(0xffffffffu, s2[n][e], msk);
    if (gid == 0)
        #pragma unroll
        for (int n = 0; n < 2; n++)
            #pragma unroll
            for (int e = 0; e < 2; e++)
                psm_s[wid][n * 8 + lm * 2 + e] = s2[n][e];
    __syncthreads();

    if (tid < NH_) {
        int h = tid;
        int blk = blockIdx.x & 63;
        float g = fmaxf(fmaxf(pmx_s[0][h], pmx_s[1][h]),
                        fmaxf(pmx_s[2][h], pmx_s[3][h]));
        float s = psm_s[0][h] + psm_s[1][h] + psm_s[2][h] + psm_s[3][h];
        pmax[((size_t)b * NH_ + h) * 64 + blk] = g;
        psum[((size_t)b * NH_ + h) * 64 + blk] = s;
    }
}

// ---------------- fold ----------------
#define FCH 16
#define NFCH (H_ / FCH)   // 64
__global__ __launch_bounds__(256)
void fold_kernel(const float* __restrict__ Wx, const float* __restrict__ Wl,
                 const float* __restrict__ pq, float* __restrict__ ufold)
{
    __shared__ float wl_s[NH_][FCH];
    const int n0 = blockIdx.x * FCH;
    const int b  = blockIdx.y;
    const int tid = threadIdx.x;

    if (tid < NH_ * FCH) {
        int h = tid >> 4, c = tid & 15;
        float v = Wl[h * H_ + n0 + c];
        if (pq) v *= pq[(size_t)b * H_ + n0 + c];
        wl_s[h][c] = v;
    }
    __syncthreads();

    const int i0 = tid * 4;
    float acc[NH_][4];
    #pragma unroll
    for (int h = 0; h < NH_; h++)
        #pragma unroll
        for (int e = 0; e < 4; e++) acc[h][e] = 0.f;

    #pragma unroll
    for (int nn = 0; nn < FCH; nn++) {
        float4 w4 = *(const float4*)(Wx + (size_t)(n0 + nn) * H_ + i0);
        #pragma unroll
        for (int h = 0; h < NH_; h++) {
            float wl = wl_s[h][nn];
            acc[h][0] = fmaf(wl, w4.x, acc[h][0]);
            acc[h][1] = fmaf(wl, w4.y, acc[h][1]);
            acc[h][2] = fmaf(wl, w4.z, acc[h][2]);
            acc[h][3] = fmaf(wl, w4.w, acc[h][3]);
        }
    }
    float* op = ufold + ((size_t)blockIdx.x * gridDim.y + b) * NH_ * H_;
    #pragma unroll
    for (int h = 0; h < NH_; h++)
        *(float4*)(op + h * H_ + i0) = *(float4*)acc[h];
}

__global__ __launch_bounds__(256)
void foldcvt_kernel(const float* __restrict__ in, __half* __restrict__ out,
                    int count, int sstride)
{
    int i = blockIdx.x * 256 + threadIdx.x;
    if (i >= count) return;
    float s = 0.f;
    #pragma unroll
    for (int n = 0; n < NFCH; n++) s += in[(size_t)n * sstride + i];
    out[i] = __float2half(s);
}

__global__ __launch_bounds__(256)
void sbias_kernel(const float* __restrict__ Wl, const float* __restrict__ bvec,
                  const float* __restrict__ badd, const float* __restrict__ pq,
                  float* __restrict__ sb)
{
    __shared__ float red[256];
    const int h = blockIdx.x, b = blockIdx.y, tid = threadIdx.x;
    float s = 0.f;
    for (int n = tid; n < H_; n += 256) {
        float v = Wl[h * H_ + n] * bvec[n];
        if (pq) v *= pq[(size_t)b * H_ + n];
        s += v;
    }
    red[tid] = s; __syncthreads();
    #pragma unroll
    for (int k2 = 128; k2; k2 >>= 1) {
        if (tid < k2) red[tid] += red[tid + k2];
        __syncthreads();
    }
    if (tid == 0) sb[b * NH_ + h] = red[0] + badd[h];
}

// ---------------- poolT with inline stats combine ----------------
#define PJ 128
#define PT 1024
#define NTC 4
__global__ __launch_bounds__(256)
void poolT_kernel(const float* __restrict__ score, const float* __restrict__ pmax,
                  const float* __restrict__ psum, const __half* __restrict__ hs,
                  float* __restrict__ ph)
{
    __shared__ float  w_s[NH_][128];
    __shared__ __half hs_s[128][PJ];
    __shared__ float  hmx[NH_], hinv[NH_];
    const int b = blockIdx.x, jc = blockIdx.y, tc = blockIdx.z;
    const int j0 = jc * PJ, t0 = tc * PT;
    const int tid = threadIdx.x;
    const int jj = (tid & 63) * 2;
    const int hg = tid >> 6;
    const uint32_t hsb = (uint32_t)__cvta_generic_to_shared(hs_s);

    // inline stats combine: h = tid>>4, lane-in-group l = tid&15, 4 entries each
    {
        const int h = tid >> 4, l = tid & 15;
        const size_t base = ((size_t)b * NH_ + h) * 64;
        float mv[4], sv[4];
        #pragma unroll
        for (int e = 0; e < 4; e++) {
            mv[e] = pmax[base + l + e * 16];
            sv[e] = psum[base + l + e * 16];
        }
        float m = fmaxf(fmaxf(mv[0], mv[1]), fmaxf(mv[2], mv[3]));
        #pragma unroll
        for (int o = 1; o <= 8; o <<= 1)
            m = fmaxf(m, __shfl_xor_sync(0xffffffffu, m, o));
        float s = 0.f;
        #pragma unroll
        for (int e = 0; e < 4; e++) s += sv[e] * __expf(mv[e] - m);
        #pragma unroll
        for (int o = 1; o <= 8; o <<= 1)
            s += __shfl_xor_sync(0xffffffffu, s, o);
        if (l == 0) { hmx[h] = m; hinv[h] = 1.f / s; }
    }
    __syncthreads();

    float acc[4][2];
    #pragma unroll
    for (int e = 0; e < 4; e++) { acc[e][0] = 0.f; acc[e][1] = 0.f; }

    for (int tt = 0; tt < PT; tt += 128) {
        #pragma unroll
        for (int l = 0; l < 8; l++) {
            int idx = l * 256 + tid;
            int h = idx >> 7, t = idx & 127;
            float raw = score[((size_t)(b * NH_ + h)) * T_ + t0 + tt + t];
            w_s[h][t] = __expf(raw - hmx[h]) * hinv[h];
        }
        #pragma unroll
        for (int l = 0; l < 8; l++) {
            int c = l * 256 + tid;
            int row = c >> 4, ch = c & 15;
            cp16(hsb + (row * PJ + ch * 8) * 2,
                 hs + ((size_t)(b * T_ + t0 + tt + row)) * H_ + j0 + ch * 8);
        }
        cp_commit();
        cp_wait<0>();
        __syncthreads();

        for (int t = 0; t < 128; t++) {
            __half2 hv = *(__half2*)&hs_s[t][jj];
            float h0 = __low2float(hv), h1 = __high2float(hv);
            #pragma unroll
            for (int e = 0; e < 4; e++) {
                float wv = w_s[hg * 4 + e][t];
                acc[e][0] = fmaf(wv, h0, acc[e][0]);
                acc[e][1] = fmaf(wv, h1, acc[e][1]);
            }
        }
        __syncthreads();
    }
    #pragma unroll
    for (int e = 0; e < 4; e++) {
        size_t o = ((size_t)tc * B_ * NH_ + (size_t)b * NH_ + hg * 4 + e) * H_ + j0 + jj;
        ph[o]     = acc[e][0];
        ph[o + 1] = acc[e][1];
    }
}

// ---------------- recon: pooled = Wx[jg,:]·(sum ph) + bx[jg] [*pqin]
// outp mode: write pooled. wts mode: also write wts[b,n,j] = fp16(Wt[n,j]*pk*256)
__global__ __launch_bounds__(256)
void recon_kernel(const float* __restrict__ ph, const float* __restrict__ Wx,
                  const float* __restrict__ bx, const float* __restrict__ pqin,
                  float* __restrict__ outp,
                  const float* __restrict__ Wt, __half* __restrict__ wts)
{
    __shared__ float phs[H_];
    __shared__ float pks[64];
    const int b = blockIdx.x >> 4, h = blockIdx.x & 15;
    const int tid = threadIdx.x, wid = tid >> 5, lane = tid & 31;
    const int j0 = h * 64;
    const size_t base = ((size_t)b * NH_ + h) * H_;
    const size_t tcs = (size_t)B_ * NH_ * H_;
    for (int i = tid; i < H_; i += 256)
        phs[i] = ph[base + i] + ph[tcs + base + i] +
                 ph[2 * tcs + base + i] + ph[3 * tcs + base + i];
    __syncthreads();

    #pragma unroll
    for (int r = 0; r < 8; r++) {
        int jg = j0 + wid * 8 + r;
        const float* wrow = Wx + (size_t)jg * H_;
        float s = 0.f;
        for (int i = lane; i < H_; i += 32) s = fmaf(wrow[i], phs[i], s);
        #pragma unroll
        for (int o = 16; o; o >>= 1) s += __shfl_xor_sync(0xffffffffu, s, o);
        if (lane == 0) {
            float v = s + bx[jg];
            if (pqin) v *= pqin[(size_t)b * H_ + jg];
            if (wts) pks[wid * 8 + r] = v * WTS_SCALE;
            else     outp[(size_t)b * H_ + jg] = v;
        }
    }

    if (wts) {
        __syncthreads();
        const int jj = lane * 2;
        const float p0 = pks[jj], p1 = pks[jj + 1];
        __half* wb = wts + (size_t)b * H_ * H_ + j0;
        const float* wtb = Wt + j0;
        for (int n = wid; n < H_; n += 8) {
            float2 w = *(const float2*)(wtb + (size_t)n * H_ + jj);
            __half2 v = __floats2half2_rn(w.x * p0, w.y * p1);
            *(__half2*)(wb + (size_t)n * H_ + jj) = v;
        }
    }
}

// ---------------- fp32 -> fp16 convert ----------------
__global__ __launch_bounds__(256)
void cvt_kernel(const float* __restrict__ src, __half* __restrict__ dst, int n8)
{
    int i = blockIdx.x * 256 + threadIdx.x;
    if (i >= n8) return;
    float4 a = ((const float4*)src)[2 * i];
    float4 b = ((const float4*)src)[2 * i + 1];
    __half2 h0 = __floats2half2_rn(a.x, a.y), h1 = __floats2half2_rn(a.z, a.w);
    __half2 h2 = __floats2half2_rn(b.x, b.y), h3 = __floats2half2_rn(b.z, b.w);
    uint4 v;
    v.x = reinterpret_cast<uint32_t&>(h0);
    v.y = reinterpret_cast<uint32_t&>(h1);
    v.z = reinterpret_cast<uint32_t&>(h2);
    v.w = reinterpret_cast<uint32_t&>(h3);
    ((uint4*)dst)[i] = v;
}

// ---------------- launch ----------------
extern "C" void kernel_launch(void* const* d_in, const int* in_sizes, int n_in,
                              void* d_out, int out_size)
{
    const float* hs   = (const float*)d_in[0];
    const float* mask = (const float*)d_in[1];
    const float* Wq   = (const float*)d_in[2];
    const float* bq   = (const float*)d_in[3];
    const float* Wk   = (const float*)d_in[4];
    const float* bk   = (const float*)d_in[5];
    const float* Wql  = (const float*)d_in[6];
    const float* bql  = (const float*)d_in[7];
    const float* Wkl  = (const float*)d_in[8];
    const float* bkl  = (const float*)d_in[9];
    const float* Wt   = (const float*)d_in[10];
    const float* bt   = (const float*)d_in[11];
    float* out = (float*)d_out;

    __half *hsh, *qh, *wqh, *wts, *uqh, *ukh;
    float *ufoldq, *ufoldk, *score, *pmax, *psum, *ph, *pq, *sb;
    cudaGetSymbolAddress((void**)&hsh, g_hsh);
    cudaGetSymbolAddress((void**)&qh, g_qh);
    cudaGetSymbolAddress((void**)&wqh, g_wqh);
    cudaGetSymbolAddress((void**)&wts, g_wts);
    cudaGetSymbolAddress((void**)&uqh, g_uqh);
    cudaGetSymbolAddress((void**)&ukh, g_ukh);
    cudaGetSymbolAddress((void**)&ufoldq, g_ufold2);
    cudaGetSymbolAddress((void**)&ufoldk, g_ufoldk);
    cudaGetSymbolAddress((void**)&score, g_score);
    cudaGetSymbolAddress((void**)&pmax, g_pmax);
    cudaGetSymbolAddress((void**)&psum, g_psum);
    cudaGetSymbolAddress((void**)&ph, g_ph);
    cudaGetSymbolAddress((void**)&pq, g_pq);
    cudaGetSymbolAddress((void**)&sb, g_sb);

    cudaFuncSetAttribute(gemm_h<0>, cudaFuncAttributeMaxDynamicSharedMemorySize, SMEM_DYN);
    cudaFuncSetAttribute(gemm_h<1>, cudaFuncAttributeMaxDynamicSharedMemorySize, SMEM_DYN);
    cudaFuncSetAttribute(score_mma, cudaFuncAttributeMaxDynamicSharedMemorySize, S_SMEM);

    // ---- fork 1: weight-only prep on side stream (legal: after evFork) ----
    cudaEventRecord(g_sp.evFork, 0);
    cudaStreamWaitEvent(g_sp.side, g_sp.evFork, 0);
    {
        int w8 = H_ * H_ / 8;
        cvt_kernel<<<(w8 + 255) / 256, 256, 0, g_sp.side>>>(Wq, wqh, w8);
        fold_kernel<<<dim3(NFCH, 1), 256, 0, g_sp.side>>>(Wq, Wql, nullptr, ufoldq);
        foldcvt_kernel<<<(NH_ * H_) / 256, 256, 0, g_sp.side>>>(ufoldq, uqh, NH_ * H_, NH_ * H_);
        sbias_kernel<<<dim3(NH_, 1), 256, 0, g_sp.side>>>(Wql, bq, bql, nullptr, sb);
        cudaEventRecord(g_sp.evA, g_sp.side);
    }

    // ---- main: hs convert (runs concurrent with weight prep) ----
    {
        int n8 = (int)((size_t)MTOT * H_ / 8);
        cvt_kernel<<<(n8 + 255) / 256, 256>>>(hs, hsh, n8);
    }
    cudaEventRecord(g_sp.evHs, 0);

    // side: q = hs @ Wq^T + bq (needs hsh + wqh)
    cudaStreamWaitEvent(g_sp.side, g_sp.evHs, 0);
    gemm_h<0><<<dim3(H_ / BN, MTOT / BM), 256, SMEM_DYN, g_sp.side>>>(
        hsh, wqh, bq, nullptr, qh, nullptr);
    cudaEventRecord(g_sp.evJoin, g_sp.side);

    // main: q-path (needs hsh + uqh/sb from side prep)
    cudaStreamWaitEvent(0, g_sp.evA, 0);
    score_mma<<<MTOT / 64, 128, S_SMEM>>>(hsh, uqh, sb, mask, score, pmax, psum, 0, 0);
    poolT_kernel<<<dim3(B_, H_ / PJ, NTC), 256>>>(score, pmax, psum, hsh, ph);
    recon_kernel<<<B_ * NH_, 256>>>(ph, Wq, bq, nullptr, pq, nullptr, nullptr);

    // main: k-path
    fold_kernel<<<dim3(NFCH, B_), 256>>>(Wk, Wkl, pq, ufoldk);
    foldcvt_kernel<<<(B_ * NH_ * H_) / 256, 256>>>(ufoldk, ukh, B_ * NH_ * H_, B_ * NH_ * H_);
    sbias_kernel<<<dim3(NH_, B_), 256>>>(Wkl, bk, bkl, pq, sb);
    score_mma<<<MTOT / 64, 128, S_SMEM>>>(hsh, ukh, sb, mask, score, pmax, psum, NH_ * H_, NH_);
    poolT_kernel<<<dim3(B_, H_ / PJ, NTC), 256>>>(score, pmax, psum, hsh, ph);
    recon_kernel<<<B_ * NH_, 256>>>(ph, Wk, bk, pq, nullptr, Wt, wts);

    // ---- join: gemm<1> needs qh (side) + wts (main) ----
    cudaStreamWaitEvent(0, g_sp.evJoin, 0);
    gemm_h<1><<<dim3(H_ / BN, MTOT / BM), 256, SMEM_DYN>>>(
        qh, wts, bt, qh, nullptr, out);
}

// round 16
// speedup vs baseline: 1.0187x; 1.0187x over previous
#include <cuda_runtime.h>
#include <cuda_fp16.h>
#include <cstdint>
#include <math.h>

// Problem constants
#define B_   8
#define T_   4096
#define H_   1024
#define NH_  16
#define HD_  64
#define MTOT (B_ * T_)          // 32768
#define SCALE 0.125f            // 1/sqrt(64)
#define WTS_SCALE 256.0f
#define WTS_INV   (1.0f / 256.0f)

// ---------------- scratch ----------------
__device__ __half g_hsh[(size_t)MTOT * H_];       // 64 MB
__device__ __half g_qh[(size_t)MTOT * H_];        // 64 MB
__device__ __half g_wqh[H_ * H_];
__device__ __half g_wts[(size_t)B_ * H_ * H_];    // 16 MB
__device__ __half g_uqh[NH_ * H_];
__device__ __half g_ukh[B_ * NH_ * H_];
__device__ float  g_ufold2[64 * NH_ * H_];        // q-fold partials [64][16][1024]
__device__ float  g_ufoldk[64 * B_ * NH_ * H_];   // k-fold partials [64][8][16][1024]
__device__ float  g_score[(size_t)B_ * NH_ * T_]; // 2 MB (raw scores)
__device__ float  g_pmax[B_ * NH_ * 64];
__device__ float  g_psum[B_ * NH_ * 64];
__device__ float  g_ph[4 * B_ * NH_ * H_];        // pooled-hs partials [4 tc][B][NH][H]
__device__ float  g_pq[B_ * H_];
__device__ float  g_pk[B_ * H_];
__device__ float  g_sb[B_ * NH_];

// ---------------- streams/events (host objects, static init) ----------------
struct StreamPack {
    cudaStream_t side;
    cudaEvent_t evFork, evHs, evA, evJoin;
    StreamPack() {
        cudaStreamCreateWithFlags(&side, cudaStreamNonBlocking);
        cudaEventCreateWithFlags(&evFork, cudaEventDisableTiming);
        cudaEventCreateWithFlags(&evHs, cudaEventDisableTiming);
        cudaEventCreateWithFlags(&evA, cudaEventDisableTiming);
        cudaEventCreateWithFlags(&evJoin, cudaEventDisableTiming);
    }
};
static StreamPack g_sp;

// ---------------- common PTX ----------------
__device__ __forceinline__ void cp16(uint32_t smem, const void* gmem) {
    asm volatile("cp.async.cg.shared.global [%0], [%1], 16;" :: "r"(smem), "l"(gmem));
}
__device__ __forceinline__ void cp_commit() { asm volatile("cp.async.commit_group;"); }
template <int N> __device__ __forceinline__ void cp_wait() {
    asm volatile("cp.async.wait_group %0;" :: "n"(N));
}
__device__ __forceinline__ void ldsm_x4(uint32_t* r, uint32_t addr) {
    asm volatile("ldmatrix.sync.aligned.m8n8.x4.shared.b16 {%0,%1,%2,%3}, [%4];"
                 : "=r"(r[0]), "=r"(r[1]), "=r"(r[2]), "=r"(r[3]) : "r"(addr));
}
__device__ __forceinline__ void mma_f16(float* c, const uint32_t* a, const uint32_t* b) {
    asm volatile(
        "mma.sync.aligned.m16n8k16.row.col.f32.f16.f16.f32 "
        "{%0,%1,%2,%3}, {%4,%5,%6,%7}, {%8,%9}, {%0,%1,%2,%3};"
        : "+f"(c[0]), "+f"(c[1]), "+f"(c[2]), "+f"(c[3])
        : "r"(a[0]), "r"(a[1]), "r"(a[2]), "r"(a[3]),
          "r"(b[0]), "r"(b[1]));
}

// =================================================================
// fp16 GEMM: block 256x128, warp 64x64 (8 warps, 4m x 2n), BK=64, 3-stage ring
// =================================================================
#define BM 256
#define BN 128
#define BKK 64
#define ROWH 72
#define STAGES 3
#define ASTG_BYTES (BM * ROWH * 2)
#define BSTG_BYTES (BN * ROWH * 2)
#define STG_BYTES  (ASTG_BYTES + BSTG_BYTES)
#define SMEM_DYN   (STAGES * STG_BYTES)      // 165888

template <int MODE>
__global__ __launch_bounds__(256, 1)
void gemm_h(const __half* __restrict__ A,
            const __half* __restrict__ W0, const float* __restrict__ bias0,
            const __half* __restrict__ addend,
            __half* __restrict__ C0h, float* __restrict__ Cf)
{
    const int K = H_, N = H_;
    extern __shared__ __half smem[];
    const uint32_t sb = (uint32_t)__cvta_generic_to_shared(smem);

    const int tid = threadIdx.x;
    const int bm  = blockIdx.y * BM;

    const __half* W = W0; const float* bias = bias0;
    int bn = blockIdx.x * BN;
    if (MODE == 1) W = W0 + (size_t)(bm / T_) * H_ * H_;

    const int wid = tid >> 5, lane = tid & 31;
    const int warp_m = wid >> 1, warp_n = wid & 1;
    const int gid = lane >> 2, lm = lane & 3;

    const int a_r = (lane & 7) + ((lane >> 3) & 1) * 8;
    const int a_c = (lane >> 4) * 8;
    const int b_r = (lane & 7) + ((lane >> 4) & 1) * 8;
    const int b_c = ((lane >> 3) & 1) * 8;

    float acc[4][8][4];
    #pragma unroll
    for (int i = 0; i < 4; i++)
        #pragma unroll
        for (int j = 0; j < 8; j++)
            #pragma unroll
            for (int r = 0; r < 4; r++) acc[i][j][r] = 0.f;

    auto issue_copy = [&](int kt, int s) {
        const int k0 = kt * BKK;
        const uint32_t ab = sb + s * STG_BYTES;
        const uint32_t bb = ab + ASTG_BYTES;
        #pragma unroll
        for (int l = 0; l < 8; l++) {
            int c = l * 256 + tid;
            int row = c >> 3, colh = (c & 7) * 8;
            cp16(ab + (row * ROWH + colh) * 2, A + (size_t)(bm + row) * K + k0 + colh);
        }
        #pragma unroll
        for (int l = 0; l < 4; l++) {
            int c = l * 256 + tid;
            int row = c >> 3, colh = (c & 7) * 8;
            cp16(bb + (row * ROWH + colh) * 2, W + (size_t)(bn + row) * K + k0 + colh);
        }
        cp_commit();
    };

    issue_copy(0, 0);
    issue_copy(1, 1);

    const int KT = K / BKK;   // 16
    for (int kt = 0; kt < KT; kt++) {
        cp_wait<1>();
        __syncthreads();
        if (kt + 2 < KT) issue_copy(kt + 2, (kt + 2) % STAGES);

        const uint32_t ab = sb + (kt % STAGES) * STG_BYTES;
        const uint32_t bb = ab + ASTG_BYTES;

        #pragma unroll
        for (int kk = 0; kk < 4; kk++) {
            const int kb = kk * 16;
            uint32_t af[4][4], bf[8][2];
            #pragma unroll
            for (int mt = 0; mt < 4; mt++)
                ldsm_x4(af[mt],
                        ab + ((warp_m * 64 + mt * 16 + a_r) * ROWH + kb + a_c) * 2);
            #pragma unroll
            for (int ntp = 0; ntp < 4; ntp++) {
                uint32_t r4[4];
                ldsm_x4(r4,
                        bb + ((warp_n * 64 + ntp * 16 + b_r) * ROWH + kb + b_c) * 2);
                bf[ntp * 2 + 0][0] = r4[0]; bf[ntp * 2 + 0][1] = r4[1];
                bf[ntp * 2 + 1][0] = r4[2]; bf[ntp * 2 + 1][1] = r4[3];
            }
            #pragma unroll
            for (int mt = 0; mt < 4; mt++)
                #pragma unroll
                for (int nt = 0; nt < 8; nt++)
                    mma_f16(acc[mt][nt], af[mt], bf[nt]);
        }
    }

    #pragma unroll
    for (int mt = 0; mt < 4; mt++) {
        #pragma unroll
        for (int nt = 0; nt < 8; nt++) {
            int row0 = bm + warp_m * 64 + mt * 16 + gid;
            int col  = bn + warp_n * 64 + nt * 8 + lm * 2;
            float b0 = bias[col], b1 = bias[col + 1];
            #pragma unroll
            for (int hh = 0; hh < 2; hh++) {
                int row = row0 + hh * 8;
                size_t off = (size_t)row * N + col;
                if (MODE == 0) {
                    __half2 v = __floats2half2_rn(acc[mt][nt][hh * 2 + 0] + b0,
                                                  acc[mt][nt][hh * 2 + 1] + b1);
                    *(__half2*)(C0h + off) = v;
                } else {
                    __half2 ad = *(const __half2*)(addend + off);
                    float2 v;
                    v.x = acc[mt][nt][hh * 2 + 0] * WTS_INV + b0 + __low2float(ad);
                    v.y = acc[mt][nt][hh * 2 + 1] * WTS_INV + b1 + __high2float(ad);
                    *(float2*)(Cf + off) = v;
                }
            }
        }
    }
}

// =================================================================
// score GEMM + partial softmax stats
// =================================================================
#define SNC  16
#define SROW 72
#define WROW 1032
#define S_QS_STG (64 * SROW * 2)
#define S_WL     (NH_ * WROW * 2)
#define S_SMEM   (S_WL + 3 * S_QS_STG)

__global__ __launch_bounds__(128)
void score_mma(const __half* __restrict__ X, const __half* __restrict__ wl_g,
               const float* __restrict__ bl, const float* __restrict__ mask,
               float* __restrict__ score, float* __restrict__ pmax,
               float* __restrict__ psum, int wl_bstride, int bl_bstride)
{
    extern __shared__ char smemc[];
    const uint32_t sb = (uint32_t)__cvta_generic_to_shared(smemc);
    const int tid = threadIdx.x, wid = tid >> 5, lane = tid & 31;
    const int bt0 = blockIdx.x * 64;
    const int b = bt0 >> 12;
    const __half* wl = wl_g + (size_t)b * wl_bstride;
    const float* blp = bl + (size_t)b * bl_bstride;

    const int a_r = (lane & 7) + ((lane >> 3) & 1) * 8;
    const int a_c = (lane >> 4) * 8;
    const int b_r = (lane & 7) + ((lane >> 4) & 1) * 8;
    const int b_c = ((lane >> 3) & 1) * 8;

    auto issue_q = [&](int kc, int s) {
        const uint32_t qb = sb + S_WL + s * S_QS_STG;
        #pragma unroll
        for (int l = 0; l < 4; l++) {
            int c = l * 128 + tid;
            int row = c >> 3, colh = (c & 7) * 8;
            cp16(qb + (row * SROW + colh) * 2,
                 X + (size_t)(bt0 + row) * H_ + kc * 64 + colh);
        }
        cp_commit();
    };

    #pragma unroll
    for (int l = 0; l < 16; l++) {
        int c = l * 128 + tid;
        int row = c >> 7, c8 = (c & 127) * 8;
        cp16(sb + (row * WROW + c8) * 2, wl + (size_t)row * H_ + c8);
    }
    issue_q(0, 0);
    issue_q(1, 1);

    float acc[2][4];
    #pragma unroll
    for (int n = 0; n < 2; n++)
        #pragma unroll
        for (int r = 0; r < 4; r++) acc[n][r] = 0.f;

    for (int kc = 0; kc < SNC; kc++) {
        cp_wait<1>();
        __syncthreads();
        if (kc + 2 < SNC) issue_q(kc + 2, (kc + 2) % 3);

        const uint32_t qb = sb + S_WL + (kc % 3) * S_QS_STG;
        #pragma unroll
        for (int kk = 0; kk < 4; kk++) {
            const int kb = kk * 16;
            uint32_t af[4], r4[4];
            ldsm_x4(af, qb + ((wid * 16 + a_r) * SROW + kb + a_c) * 2);
            ldsm_x4(r4, sb + (b_r * WROW + kc * 64 + kb + b_c) * 2);
            uint32_t bf0[2] = { r4[0], r4[1] }, bf1[2] = { r4[2], r4[3] };
            mma_f16(acc[0], af, bf0);
            mma_f16(acc[1], af, bf1);
        }
    }

    const int gid = lane >> 2, lm = lane & 3;
    const int bt = bt0 + wid * 16 + gid;
    const int t = bt & (T_ - 1);
    const float madd0 = (1.f - mask[bt]) * -10000.f;
    const float madd8 = (1.f - mask[bt + 8]) * -10000.f;

    float sc[2][2][2];
    #pragma unroll
    for (int n = 0; n < 2; n++) {
        #pragma unroll
        for (int e = 0; e < 2; e++) {
            int h = n * 8 + lm * 2 + e;
            sc[n][e][0] = SCALE * (acc[n][e]     + blp[h]) + madd0;
            sc[n][e][1] = SCALE * (acc[n][2 + e] + blp[h]) + madd8;
            float* sp = score + ((size_t)b * NH_ + h) * T_;
            sp[t]     = sc[n][e][0];
            sp[t + 8] = sc[n][e][1];
        }
    }

    __shared__ float pmx_s[4][NH_], psm_s[4][NH_];
    float m[2][2];
    #pragma unroll
    for (int n = 0; n < 2; n++)
        #pragma unroll
        for (int e = 0; e < 2; e++) m[n][e] = fmaxf(sc[n][e][0], sc[n][e][1]);
    #pragma unroll
    for (int msk = 4; msk <= 16; msk <<= 1)
        #pragma unroll
        for (int n = 0; n < 2; n++)
            #pragma unroll
            for (int e = 0; e < 2; e++)
                m[n][e] = fmaxf(m[n][e], __shfl_xor_sync(0xffffffffu, m[n][e], msk));
    if (gid == 0)
        #pragma unroll
        for (int n = 0; n < 2; n++)
            #pragma unroll
            for (int e = 0; e < 2; e++)
                pmx_s[wid][n * 8 + lm * 2 + e] = m[n][e];
    __syncthreads();

    float s2[2][2];
    #pragma unroll
    for (int n = 0; n < 2; n++)
        #pragma unroll
        for (int e = 0; e < 2; e++) {
            int h = n * 8 + lm * 2 + e;
            float g = fmaxf(fmaxf(pmx_s[0][h], pmx_s[1][h]),
                            fmaxf(pmx_s[2][h], pmx_s[3][h]));
            s2[n][e] = __expf(sc[n][e][0] - g) + __expf(sc[n][e][1] - g);
        }
    #pragma unroll
    for (int msk = 4; msk <= 16; msk <<= 1)
        #pragma unroll
        for (int n = 0; n < 2; n++)
            #pragma unroll
            for (int e = 0; e < 2; e++)
                s2[n][e] += __shfl_xor_sync(0xffffffffu, s2[n][e], msk);
    if (gid == 0)
        #pragma unroll
        for (int n = 0; n < 2; n++)
            #pragma unroll
            for (int e = 0; e < 2; e++)
                psm_s[wid][n * 8 + lm * 2 + e] = s2[n][e];
    __syncthreads();

    if (tid < NH_) {
        int h = tid;
        int blk = blockIdx.x & 63;
        float g = fmaxf(fmaxf(pmx_s[0][h], pmx_s[1][h]),
                        fmaxf(pmx_s[2][h], pmx_s[3][h]));
        float s = psm_s[0][h] + psm_s[1][h] + psm_s[2][h] + psm_s[3][h];
        pmax[((size_t)b * NH_ + h) * 64 + blk] = g;
        psum[((size_t)b * NH_ + h) * 64 + blk] = s;
    }
}

// ---------------- fold ----------------
#define FCH 16
#define NFCH (H_ / FCH)   // 64
__global__ __launch_bounds__(256)
void fold_kernel(const float* __restrict__ Wx, const float* __restrict__ Wl,
                 const float* __restrict__ pq, float* __restrict__ ufold)
{
    __shared__ float wl_s[NH_][FCH];
    const int n0 = blockIdx.x * FCH;
    const int b  = blockIdx.y;
    const int tid = threadIdx.x;

    if (tid < NH_ * FCH) {
        int h = tid >> 4, c = tid & 15;
        float v = Wl[h * H_ + n0 + c];
        if (pq) v *= pq[(size_t)b * H_ + n0 + c];
        wl_s[h][c] = v;
    }
    __syncthreads();

    const int i0 = tid * 4;
    float acc[NH_][4];
    #pragma unroll
    for (int h = 0; h < NH_; h++)
        #pragma unroll
        for (int e = 0; e < 4; e++) acc[h][e] = 0.f;

    #pragma unroll
    for (int nn = 0; nn < FCH; nn++) {
        float4 w4 = *(const float4*)(Wx + (size_t)(n0 + nn) * H_ + i0);
        #pragma unroll
        for (int h = 0; h < NH_; h++) {
            float wl = wl_s[h][nn];
            acc[h][0] = fmaf(wl, w4.x, acc[h][0]);
            acc[h][1] = fmaf(wl, w4.y, acc[h][1]);
            acc[h][2] = fmaf(wl, w4.z, acc[h][2]);
            acc[h][3] = fmaf(wl, w4.w, acc[h][3]);
        }
    }
    float* op = ufold + ((size_t)blockIdx.x * gridDim.y + b) * NH_ * H_;
    #pragma unroll
    for (int h = 0; h < NH_; h++)
        *(float4*)(op + h * H_ + i0) = *(float4*)acc[h];
}

__global__ __launch_bounds__(256)
void foldcvt_kernel(const float* __restrict__ in, __half* __restrict__ out,
                    int count, int sstride)
{
    int i = blockIdx.x * 256 + threadIdx.x;
    if (i >= count) return;
    float s = 0.f;
    #pragma unroll
    for (int n = 0; n < NFCH; n++) s += in[(size_t)n * sstride + i];
    out[i] = __float2half(s);
}

__global__ __launch_bounds__(256)
void sbias_kernel(const float* __restrict__ Wl, const float* __restrict__ bvec,
                  const float* __restrict__ badd, const float* __restrict__ pq,
                  float* __restrict__ sb)
{
    __shared__ float red[256];
    const int h = blockIdx.x, b = blockIdx.y, tid = threadIdx.x;
    float s = 0.f;
    for (int n = tid; n < H_; n += 256) {
        float v = Wl[h * H_ + n] * bvec[n];
        if (pq) v *= pq[(size_t)b * H_ + n];
        s += v;
    }
    red[tid] = s; __syncthreads();
    #pragma unroll
    for (int k2 = 128; k2; k2 >>= 1) {
        if (tid < k2) red[tid] += red[tid + k2];
        __syncthreads();
    }
    if (tid == 0) sb[b * NH_ + h] = red[0] + badd[h];
}

// ---------------- poolT with inline stats combine ----------------
#define PJ 128
#define PT 1024
#define NTC 4
__global__ __launch_bounds__(256)
void poolT_kernel(const float* __restrict__ score, const float* __restrict__ pmax,
                  const float* __restrict__ psum, const __half* __restrict__ hs,
                  float* __restrict__ ph)
{
    __shared__ float  w_s[NH_][128];
    __shared__ __half hs_s[128][PJ];
    __shared__ float  hmx[NH_], hinv[NH_];
    const int b = blockIdx.x, jc = blockIdx.y, tc = blockIdx.z;
    const int j0 = jc * PJ, t0 = tc * PT;
    const int tid = threadIdx.x;
    const int jj = (tid & 63) * 2;
    const int hg = tid >> 6;
    const uint32_t hsb = (uint32_t)__cvta_generic_to_shared(hs_s);

    // inline stats combine
    {
        const int h = tid >> 4, l = tid & 15;
        const size_t base = ((size_t)b * NH_ + h) * 64;
        float mv[4], sv[4];
        #pragma unroll
        for (int e = 0; e < 4; e++) {
            mv[e] = pmax[base + l + e * 16];
            sv[e] = psum[base + l + e * 16];
        }
        float m = fmaxf(fmaxf(mv[0], mv[1]), fmaxf(mv[2], mv[3]));
        #pragma unroll
        for (int o = 1; o <= 8; o <<= 1)
            m = fmaxf(m, __shfl_xor_sync(0xffffffffu, m, o));
        float s = 0.f;
        #pragma unroll
        for (int e = 0; e < 4; e++) s += sv[e] * __expf(mv[e] - m);
        #pragma unroll
        for (int o = 1; o <= 8; o <<= 1)
            s += __shfl_xor_sync(0xffffffffu, s, o);
        if (l == 0) { hmx[h] = m; hinv[h] = 1.f / s; }
    }
    __syncthreads();

    float acc[4][2];
    #pragma unroll
    for (int e = 0; e < 4; e++) { acc[e][0] = 0.f; acc[e][1] = 0.f; }

    for (int tt = 0; tt < PT; tt += 128) {
        #pragma unroll
        for (int l = 0; l < 8; l++) {
            int idx = l * 256 + tid;
            int h = idx >> 7, t = idx & 127;
            float raw = score[((size_t)(b * NH_ + h)) * T_ + t0 + tt + t];
            w_s[h][t] = __expf(raw - hmx[h]) * hinv[h];
        }
        #pragma unroll
        for (int l = 0; l < 8; l++) {
            int c = l * 256 + tid;
            int row = c >> 4, ch = c & 15;
            cp16(hsb + (row * PJ + ch * 8) * 2,
                 hs + ((size_t)(b * T_ + t0 + tt + row)) * H_ + j0 + ch * 8);
        }
        cp_commit();
        cp_wait<0>();
        __syncthreads();

        for (int t = 0; t < 128; t++) {
            __half2 hv = *(__half2*)&hs_s[t][jj];
            float h0 = __low2float(hv), h1 = __high2float(hv);
            #pragma unroll
            for (int e = 0; e < 4; e++) {
                float wv = w_s[hg * 4 + e][t];
                acc[e][0] = fmaf(wv, h0, acc[e][0]);
                acc[e][1] = fmaf(wv, h1, acc[e][1]);
            }
        }
        __syncthreads();
    }
    #pragma unroll
    for (int e = 0; e < 4; e++) {
        size_t o = ((size_t)tc * B_ * NH_ + (size_t)b * NH_ + hg * 4 + e) * H_ + j0 + jj;
        ph[o]     = acc[e][0];
        ph[o + 1] = acc[e][1];
    }
}

// ---------------- recon: out[b, jg] = Wx[jg,:]·(sum ph)[b,h,:] + bx[jg], [*pqin]
__global__ __launch_bounds__(256)
void recon_kernel(const float* __restrict__ ph, const float* __restrict__ Wx,
                  const float* __restrict__ bx, const float* __restrict__ pqin,
                  float* __restrict__ outp)
{
    __shared__ float phs[H_];
    const int b = blockIdx.x >> 4, h = blockIdx.x & 15;
    const int tid = threadIdx.x, wid = tid >> 5, lane = tid & 31;
    const size_t base = ((size_t)b * NH_ + h) * H_;
    const size_t tcs = (size_t)B_ * NH_ * H_;
    for (int i = tid; i < H_; i += 256)
        phs[i] = ph[base + i] + ph[tcs + base + i] +
                 ph[2 * tcs + base + i] + ph[3 * tcs + base + i];
    __syncthreads();

    #pragma unroll
    for (int r = 0; r < 8; r++) {
        int jg = h * 64 + wid * 8 + r;
        const float* wrow = Wx + (size_t)jg * H_;
        float s = 0.f;
        for (int i = lane; i < H_; i += 32) s = fmaf(wrow[i], phs[i], s);
        #pragma unroll
        for (int o = 16; o; o >>= 1) s += __shfl_xor_sync(0xffffffffu, s, o);
        if (lane == 0) {
            float v = s + bx[jg];
            size_t oo = (size_t)b * H_ + jg;
            if (pqin) v *= pqin[oo];
            outp[oo] = v;
        }
    }
}

// ---------------- fp32 -> fp16 convert ----------------
__global__ __launch_bounds__(256)
void cvt_kernel(const float* __restrict__ src, __half* __restrict__ dst, int n8)
{
    int i = blockIdx.x * 256 + threadIdx.x;
    if (i >= n8) return;
    float4 a = ((const float4*)src)[2 * i];
    float4 b = ((const float4*)src)[2 * i + 1];
    __half2 h0 = __floats2half2_rn(a.x, a.y), h1 = __floats2half2_rn(a.z, a.w);
    __half2 h2 = __floats2half2_rn(b.x, b.y), h3 = __floats2half2_rn(b.z, b.w);
    uint4 v;
    v.x = reinterpret_cast<uint32_t&>(h0);
    v.y = reinterpret_cast<uint32_t&>(h1);
    v.z = reinterpret_cast<uint32_t&>(h2);
    v.w = reinterpret_cast<uint32_t&>(h3);
    ((uint4*)dst)[i] = v;
}

// ---------------- wts[b,n,j] = fp16(Wt[n,j] * pk[b,j] * WTS_SCALE) ----------------
__global__ __launch_bounds__(256)
void scalew_kernel(const float* __restrict__ Wt, const float* __restrict__ pk,
                   __half* __restrict__ wts)
{
    size_t i = (size_t)blockIdx.x * 256 + threadIdx.x;
    size_t e = i * 4;
    int b = (int)(e >> 20);
    int r = (int)(e & (H_ * H_ - 1));
    int j = r & (H_ - 1);
    float4 w = *(const float4*)(Wt + r);
    float4 s = *(const float4*)(pk + (size_t)b * H_ + j);
    __half2 lo = __floats2half2_rn(w.x * s.x * WTS_SCALE, w.y * s.y * WTS_SCALE);
    __half2 hi = __floats2half2_rn(w.z * s.z * WTS_SCALE, w.w * s.w * WTS_SCALE);
    uint2 v;
    v.x = reinterpret_cast<uint32_t&>(lo);
    v.y = reinterpret_cast<uint32_t&>(hi);
    *(uint2*)(wts + e) = v;
}

// ---------------- launch ----------------
extern "C" void kernel_launch(void* const* d_in, const int* in_sizes, int n_in,
                              void* d_out, int out_size)
{
    const float* hs   = (const float*)d_in[0];
    const float* mask = (const float*)d_in[1];
    const float* Wq   = (const float*)d_in[2];
    const float* bq   = (const float*)d_in[3];
    const float* Wk   = (const float*)d_in[4];
    const float* bk   = (const float*)d_in[5];
    const float* Wql  = (const float*)d_in[6];
    const float* bql  = (const float*)d_in[7];
    const float* Wkl  = (const float*)d_in[8];
    const float* bkl  = (const float*)d_in[9];
    const float* Wt   = (const float*)d_in[10];
    const float* bt   = (const float*)d_in[11];
    float* out = (float*)d_out;

    __half *hsh, *qh, *wqh, *wts, *uqh, *ukh;
    float *ufoldq, *ufoldk, *score, *pmax, *psum, *ph, *pq, *pk, *sb;
    cudaGetSymbolAddress((void**)&hsh, g_hsh);
    cudaGetSymbolAddress((void**)&qh, g_qh);
    cudaGetSymbolAddress((void**)&wqh, g_wqh);
    cudaGetSymbolAddress((void**)&wts, g_wts);
    cudaGetSymbolAddress((void**)&uqh, g_uqh);
    cudaGetSymbolAddress((void**)&ukh, g_ukh);
    cudaGetSymbolAddress((void**)&ufoldq, g_ufold2);
    cudaGetSymbolAddress((void**)&ufoldk, g_ufoldk);
    cudaGetSymbolAddress((void**)&score, g_score);
    cudaGetSymbolAddress((void**)&pmax, g_pmax);
    cudaGetSymbolAddress((void**)&psum, g_psum);
    cudaGetSymbolAddress((void**)&ph, g_ph);
    cudaGetSymbolAddress((void**)&pq, g_pq);
    cudaGetSymbolAddress((void**)&pk, g_pk);
    cudaGetSymbolAddress((void**)&sb, g_sb);

    cudaFuncSetAttribute(gemm_h<0>, cudaFuncAttributeMaxDynamicSharedMemorySize, SMEM_DYN);
    cudaFuncSetAttribute(gemm_h<1>, cudaFuncAttributeMaxDynamicSharedMemorySize, SMEM_DYN);
    cudaFuncSetAttribute(score_mma, cudaFuncAttributeMaxDynamicSharedMemorySize, S_SMEM);

    // ---- fork 1: weight-only prep on side stream (legal: after evFork) ----
    cudaEventRecord(g_sp.evFork, 0);
    cudaStreamWaitEvent(g_sp.side, g_sp.evFork, 0);
    {
        int w8 = H_ * H_ / 8;
        cvt_kernel<<<(w8 + 255) / 256, 256, 0, g_sp.side>>>(Wq, wqh, w8);
        fold_kernel<<<dim3(NFCH, 1), 256, 0, g_sp.side>>>(Wq, Wql, nullptr, ufoldq);
        foldcvt_kernel<<<(NH_ * H_) / 256, 256, 0, g_sp.side>>>(ufoldq, uqh, NH_ * H_, NH_ * H_);
        sbias_kernel<<<dim3(NH_, 1), 256, 0, g_sp.side>>>(Wql, bq, bql, nullptr, sb);
        cudaEventRecord(g_sp.evA, g_sp.side);
    }

    // ---- main: hs convert (concurrent with weight prep) ----
    {
        int n8 = (int)((size_t)MTOT * H_ / 8);
        cvt_kernel<<<(n8 + 255) / 256, 256>>>(hs, hsh, n8);
    }
    cudaEventRecord(g_sp.evHs, 0);

    // side: q = hs @ Wq^T + bq (needs hsh + wqh)
    cudaStreamWaitEvent(g_sp.side, g_sp.evHs, 0);
    gemm_h<0><<<dim3(H_ / BN, MTOT / BM), 256, SMEM_DYN, g_sp.side>>>(
        hsh, wqh, bq, nullptr, qh, nullptr);
    cudaEventRecord(g_sp.evJoin, g_sp.side);

    // main: q-path (needs hsh + uqh/sb from side prep)
    cudaStreamWaitEvent(0, g_sp.evA, 0);
    score_mma<<<MTOT / 64, 128, S_SMEM>>>(hsh, uqh, sb, mask, score, pmax, psum, 0, 0);
    poolT_kernel<<<dim3(B_, H_ / PJ, NTC), 256>>>(score, pmax, psum, hsh, ph);
    recon_kernel<<<B_ * NH_, 256>>>(ph, Wq, bq, nullptr, pq);

    // main: k-path
    fold_kernel<<<dim3(NFCH, B_), 256>>>(Wk, Wkl, pq, ufoldk);
    foldcvt_kernel<<<(B_ * NH_ * H_) / 256, 256>>>(ufoldk, ukh, B_ * NH_ * H_, B_ * NH_ * H_);
    sbias_kernel<<<dim3(NH_, B_), 256>>>(Wkl, bk, bkl, pq, sb);
    score_mma<<<MTOT / 64, 128, S_SMEM>>>(hsh, ukh, sb, mask, score, pmax, psum, NH_ * H_, NH_);
    poolT_kernel<<<dim3(B_, H_ / PJ, NTC), 256>>>(score, pmax, psum, hsh, ph);
    recon_kernel<<<B_ * NH_, 256>>>(ph, Wk, bk, pq, pk);

    // main: wts[b] = fp16(Wt * pk[b] * 256) (wide grid)
    scalew_kernel<<<(B_ * H_ * H_ / 4 + 255) / 256, 256>>>(Wt, pk, wts);

    // ---- join: gemm<1> needs qh (side) + wts (main) ----
    cudaStreamWaitEvent(0, g_sp.evJoin, 0);
    gemm_h<1><<<dim3(H_ / BN, MTOT / BM), 256, SMEM_DYN>>>(
        qh, wts, bt, qh, nullptr, out);
}

// round 17
// speedup vs baseline: 1.1054x; 1.0850x over previous
#include <cuda_runtime.h>
#include <cuda_fp16.h>
#include <cstdint>
#include <math.h>

// Problem constants
#define B_   8
#define T_   4096
#define H_   1024
#define NH_  16
#define HD_  64
#define MTOT (B_ * T_)          // 32768
#define SCALE 0.125f            // 1/sqrt(64)
#define WTS_SCALE 256.0f
#define WTS_INV   (1.0f / 256.0f)

// ---------------- scratch ----------------
__device__ __half g_hsh[(size_t)MTOT * H_];       // 64 MB
__device__ __half g_qh[(size_t)MTOT * H_];        // 64 MB
__device__ __half g_wqh[H_ * H_];
__device__ __half g_wts[(size_t)B_ * H_ * H_];    // 16 MB
__device__ __half g_uqh[NH_ * H_];
__device__ __half g_ukh[B_ * NH_ * H_];
__device__ float  g_ufold2[64 * NH_ * H_];        // q-fold partials [64][16][1024]
__device__ float  g_ufoldk[64 * B_ * NH_ * H_];   // k-fold partials [64][8][16][1024]
__device__ float  g_score[(size_t)B_ * NH_ * T_]; // 2 MB (raw scores)
__device__ float  g_pmax[B_ * NH_ * 64];
__device__ float  g_psum[B_ * NH_ * 64];
__device__ float2 g_stat[B_ * NH_];
__device__ float  g_ph[4 * B_ * NH_ * H_];        // pooled-hs partials [4 tc][B][NH][H]
__device__ float  g_pq[B_ * H_];
__device__ float  g_pk[B_ * H_];
__device__ float  g_sb[B_ * NH_];

// ---------------- streams/events (host objects, static init) ----------------
struct StreamPack {
    cudaStream_t side;
    cudaEvent_t evFork, evJoin;
    StreamPack() {
        cudaStreamCreateWithFlags(&side, cudaStreamNonBlocking);
        cudaEventCreateWithFlags(&evFork, cudaEventDisableTiming);
        cudaEventCreateWithFlags(&evJoin, cudaEventDisableTiming);
    }
};
static StreamPack g_sp;

// ---------------- common PTX ----------------
__device__ __forceinline__ void cp16(uint32_t smem, const void* gmem) {
    asm volatile("cp.async.cg.shared.global [%0], [%1], 16;" :: "r"(smem), "l"(gmem));
}
__device__ __forceinline__ void cp_commit() { asm volatile("cp.async.commit_group;"); }
template <int N> __device__ __forceinline__ void cp_wait() {
    asm volatile("cp.async.wait_group %0;" :: "n"(N));
}
__device__ __forceinline__ void ldsm_x4(uint32_t* r, uint32_t addr) {
    asm volatile("ldmatrix.sync.aligned.m8n8.x4.shared.b16 {%0,%1,%2,%3}, [%4];"
                 : "=r"(r[0]), "=r"(r[1]), "=r"(r[2]), "=r"(r[3]) : "r"(addr));
}
__device__ __forceinline__ void mma_f16(float* c, const uint32_t* a, const uint32_t* b) {
    asm volatile(
        "mma.sync.aligned.m16n8k16.row.col.f32.f16.f16.f32 "
        "{%0,%1,%2,%3}, {%4,%5,%6,%7}, {%8,%9}, {%0,%1,%2,%3};"
        : "+f"(c[0]), "+f"(c[1]), "+f"(c[2]), "+f"(c[3])
        : "r"(a[0]), "r"(a[1]), "r"(a[2]), "r"(a[3]),
          "r"(b[0]), "r"(b[1]));
}

// =================================================================
// fp16 GEMM: block 256x128, warp 64x64 (8 warps, 4m x 2n), BK=64, 4-stage ring
// =================================================================
#define BM 256
#define BN 128
#define BKK 64
#define ROWH 72
#define STAGES 4
#define ASTG_BYTES (BM * ROWH * 2)
#define BSTG_BYTES (BN * ROWH * 2)
#define STG_BYTES  (ASTG_BYTES + BSTG_BYTES)
#define SMEM_DYN   (STAGES * STG_BYTES)      // 221184

template <int MODE>
__global__ __launch_bounds__(256, 1)
void gemm_h(const __half* __restrict__ A,
            const __half* __restrict__ W0, const float* __restrict__ bias0,
            const __half* __restrict__ addend,
            __half* __restrict__ C0h, float* __restrict__ Cf)
{
    const int K = H_, N = H_;
    extern __shared__ __half smem[];
    const uint32_t sb = (uint32_t)__cvta_generic_to_shared(smem);

    const int tid = threadIdx.x;
    const int bm  = blockIdx.y * BM;

    const __half* W = W0; const float* bias = bias0;
    int bn = blockIdx.x * BN;
    if (MODE == 1) W = W0 + (size_t)(bm / T_) * H_ * H_;

    const int wid = tid >> 5, lane = tid & 31;
    const int warp_m = wid >> 1, warp_n = wid & 1;
    const int gid = lane >> 2, lm = lane & 3;

    const int a_r = (lane & 7) + ((lane >> 3) & 1) * 8;
    const int a_c = (lane >> 4) * 8;
    const int b_r = (lane & 7) + ((lane >> 4) & 1) * 8;
    const int b_c = ((lane >> 3) & 1) * 8;

    float acc[4][8][4];
    #pragma unroll
    for (int i = 0; i < 4; i++)
        #pragma unroll
        for (int j = 0; j < 8; j++)
            #pragma unroll
            for (int r = 0; r < 4; r++) acc[i][j][r] = 0.f;

    auto issue_copy = [&](int kt, int s) {
        const int k0 = kt * BKK;
        const uint32_t ab = sb + s * STG_BYTES;
        const uint32_t bb = ab + ASTG_BYTES;
        #pragma unroll
        for (int l = 0; l < 8; l++) {
            int c = l * 256 + tid;
            int row = c >> 3, colh = (c & 7) * 8;
            cp16(ab + (row * ROWH + colh) * 2, A + (size_t)(bm + row) * K + k0 + colh);
        }
        #pragma unroll
        for (int l = 0; l < 4; l++) {
            int c = l * 256 + tid;
            int row = c >> 3, colh = (c & 7) * 8;
            cp16(bb + (row * ROWH + colh) * 2, W + (size_t)(bn + row) * K + k0 + colh);
        }
        cp_commit();
    };

    issue_copy(0, 0);
    issue_copy(1, 1);
    issue_copy(2, 2);

    const int KT = K / BKK;   // 16
    for (int kt = 0; kt < KT; kt++) {
        cp_wait<STAGES - 2>();       // chunk kt resident; 2 chunks stay in flight
        __syncthreads();
        if (kt + 3 < KT) issue_copy(kt + 3, (kt + 3) & 3);   // stage (kt-1)%4: consumed

        const uint32_t ab = sb + (kt & 3) * STG_BYTES;
        const uint32_t bb = ab + ASTG_BYTES;

        #pragma unroll
        for (int kk = 0; kk < 4; kk++) {
            const int kb = kk * 16;
            uint32_t af[4][4], bf[8][2];
            #pragma unroll
            for (int mt = 0; mt < 4; mt++)
                ldsm_x4(af[mt],
                        ab + ((warp_m * 64 + mt * 16 + a_r) * ROWH + kb + a_c) * 2);
            #pragma unroll
            for (int ntp = 0; ntp < 4; ntp++) {
                uint32_t r4[4];
                ldsm_x4(r4,
                        bb + ((warp_n * 64 + ntp * 16 + b_r) * ROWH + kb + b_c) * 2);
                bf[ntp * 2 + 0][0] = r4[0]; bf[ntp * 2 + 0][1] = r4[1];
                bf[ntp * 2 + 1][0] = r4[2]; bf[ntp * 2 + 1][1] = r4[3];
            }
            #pragma unroll
            for (int mt = 0; mt < 4; mt++)
                #pragma unroll
                for (int nt = 0; nt < 8; nt++)
                    mma_f16(acc[mt][nt], af[mt], bf[nt]);
        }
    }

    #pragma unroll
    for (int mt = 0; mt < 4; mt++) {
        #pragma unroll
        for (int nt = 0; nt < 8; nt++) {
            int row0 = bm + warp_m * 64 + mt * 16 + gid;
            int col  = bn + warp_n * 64 + nt * 8 + lm * 2;
            float b0 = bias[col], b1 = bias[col + 1];
            #pragma unroll
            for (int hh = 0; hh < 2; hh++) {
                int row = row0 + hh * 8;
                size_t off = (size_t)row * N + col;
                if (MODE == 0) {
                    __half2 v = __floats2half2_rn(acc[mt][nt][hh * 2 + 0] + b0,
                                                  acc[mt][nt][hh * 2 + 1] + b1);
                    *(__half2*)(C0h + off) = v;
                } else {
                    __half2 ad = *(const __half2*)(addend + off);
                    float2 v;
                    v.x = acc[mt][nt][hh * 2 + 0] * WTS_INV + b0 + __low2float(ad);
                    v.y = acc[mt][nt][hh * 2 + 1] * WTS_INV + b1 + __high2float(ad);
                    *(float2*)(Cf + off) = v;
                }
            }
        }
    }
}

// =================================================================
// score GEMM + partial softmax stats
// =================================================================
#define SNC  16
#define SROW 72
#define WROW 1032
#define S_QS_STG (64 * SROW * 2)
#define S_WL     (NH_ * WROW * 2)
#define S_SMEM   (S_WL + 3 * S_QS_STG)

__global__ __launch_bounds__(128)
void score_mma(const __half* __restrict__ X, const __half* __restrict__ wl_g,
               const float* __restrict__ bl, const float* __restrict__ mask,
               float* __restrict__ score, float* __restrict__ pmax,
               float* __restrict__ psum, int wl_bstride, int bl_bstride)
{
    extern __shared__ char smemc[];
    const uint32_t sb = (uint32_t)__cvta_generic_to_shared(smemc);
    const int tid = threadIdx.x, wid = tid >> 5, lane = tid & 31;
    const int bt0 = blockIdx.x * 64;
    const int b = bt0 >> 12;
    const __half* wl = wl_g + (size_t)b * wl_bstride;
    const float* blp = bl + (size_t)b * bl_bstride;

    const int a_r = (lane & 7) + ((lane >> 3) & 1) * 8;
    const int a_c = (lane >> 4) * 8;
    const int b_r = (lane & 7) + ((lane >> 4) & 1) * 8;
    const int b_c = ((lane >> 3) & 1) * 8;

    auto issue_q = [&](int kc, int s) {
        const uint32_t qb = sb + S_WL + s * S_QS_STG;
        #pragma unroll
        for (int l = 0; l < 4; l++) {
            int c = l * 128 + tid;
            int row = c >> 3, colh = (c & 7) * 8;
            cp16(qb + (row * SROW + colh) * 2,
                 X + (size_t)(bt0 + row) * H_ + kc * 64 + colh);
        }
        cp_commit();
    };

    #pragma unroll
    for (int l = 0; l < 16; l++) {
        int c = l * 128 + tid;
        int row = c >> 7, c8 = (c & 127) * 8;
        cp16(sb + (row * WROW + c8) * 2, wl + (size_t)row * H_ + c8);
    }
    issue_q(0, 0);
    issue_q(1, 1);

    float acc[2][4];
    #pragma unroll
    for (int n = 0; n < 2; n++)
        #pragma unroll
        for (int r = 0; r < 4; r++) acc[n][r] = 0.f;

    for (int kc = 0; kc < SNC; kc++) {
        cp_wait<1>();
        __syncthreads();
        if (kc + 2 < SNC) issue_q(kc + 2, (kc + 2) % 3);

        const uint32_t qb = sb + S_WL + (kc % 3) * S_QS_STG;
        #pragma unroll
        for (int kk = 0; kk < 4; kk++) {
            const int kb = kk * 16;
            uint32_t af[4], r4[4];
            ldsm_x4(af, qb + ((wid * 16 + a_r) * SROW + kb + a_c) * 2);
            ldsm_x4(r4, sb + (b_r * WROW + kc * 64 + kb + b_c) * 2);
            uint32_t bf0[2] = { r4[0], r4[1] }, bf1[2] = { r4[2], r4[3] };
            mma_f16(acc[0], af, bf0);
            mma_f16(acc[1], af, bf1);
        }
    }

    const int gid = lane >> 2, lm = lane & 3;
    const int bt = bt0 + wid * 16 + gid;
    const int t = bt & (T_ - 1);
    const float madd0 = (1.f - mask[bt]) * -10000.f;
    const float madd8 = (1.f - mask[bt + 8]) * -10000.f;

    float sc[2][2][2];
    #pragma unroll
    for (int n = 0; n < 2; n++) {
        #pragma unroll
        for (int e = 0; e < 2; e++) {
            int h = n * 8 + lm * 2 + e;
            sc[n][e][0] = SCALE * (acc[n][e]     + blp[h]) + madd0;
            sc[n][e][1] = SCALE * (acc[n][2 + e] + blp[h]) + madd8;
            float* sp = score + ((size_t)b * NH_ + h) * T_;
            sp[t]     = sc[n][e][0];
            sp[t + 8] = sc[n][e][1];
        }
    }

    __shared__ float pmx_s[4][NH_], psm_s[4][NH_];
    float m[2][2];
    #pragma unroll
    for (int n = 0; n < 2; n++)
        #pragma unroll
        for (int e = 0; e < 2; e++) m[n][e] = fmaxf(sc[n][e][0], sc[n][e][1]);
    #pragma unroll
    for (int msk = 4; msk <= 16; msk <<= 1)
        #pragma unroll
        for (int n = 0; n < 2; n++)
            #pragma unroll
            for (int e = 0; e < 2; e++)
                m[n][e] = fmaxf(m[n][e], __shfl_xor_sync(0xffffffffu, m[n][e], msk));
    if (gid == 0)
        #pragma unroll
        for (int n = 0; n < 2; n++)
            #pragma unroll
            for (int e = 0; e < 2; e++)
                pmx_s[wid][n * 8 + lm * 2 + e] = m[n][e];
    __syncthreads();

    float s2[2][2];
    #pragma unroll
    for (int n = 0; n < 2; n++)
        #pragma unroll
        for (int e = 0; e < 2; e++) {
            int h = n * 8 + lm * 2 + e;
            float g = fmaxf(fmaxf(pmx_s[0][h], pmx_s[1][h]),
                            fmaxf(pmx_s[2][h], pmx_s[3][h]));
            s2[n][e] = __expf(sc[n][e][0] - g) + __expf(sc[n][e][1] - g);
        }
    #pragma unroll
    for (int msk = 4; msk <= 16; msk <<= 1)
        #pragma unroll
        for (int n = 0; n < 2; n++)
            #pragma unroll
            for (int e = 0; e < 2; e++)
                s2[n][e] += __shfl_xor_sync(0xffffffffu, s2[n][e], msk);
    if (gid == 0)
        #pragma unroll
        for (int n = 0; n < 2; n++)
            #pragma unroll
            for (int e = 0; e < 2; e++)
                psm_s[wid][n * 8 + lm * 2 + e] = s2[n][e];
    __syncthreads();

    if (tid < NH_) {
        int h = tid;
        int blk = blockIdx.x & 63;
        float g = fmaxf(fmaxf(pmx_s[0][h], pmx_s[1][h]),
                        fmaxf(pmx_s[2][h], pmx_s[3][h]));
        float s = psm_s[0][h] + psm_s[1][h] + psm_s[2][h] + psm_s[3][h];
        pmax[((size_t)b * NH_ + h) * 64 + blk] = g;
        psum[((size_t)b * NH_ + h) * 64 + blk] = s;
    }
}

// ---------------- combine 64 partials per (b,h) ----------------
__global__ __launch_bounds__(64)
void stats_comb(const float* __restrict__ pmax, const float* __restrict__ psum,
                float2* __restrict__ stat)
{
    const int bh = blockIdx.x, tid = threadIdx.x;
    float mx = pmax[(size_t)bh * 64 + tid];
    float sm = psum[(size_t)bh * 64 + tid];
    float m = mx;
    #pragma unroll
    for (int o = 16; o; o >>= 1) m = fmaxf(m, __shfl_xor_sync(0xffffffffu, m, o));
    __shared__ float wm[2], ws[2];
    if ((tid & 31) == 0) wm[tid >> 5] = m;
    __syncthreads();
    const float M = fmaxf(wm[0], wm[1]);
    float s = sm * __expf(mx - M);
    #pragma unroll
    for (int o = 16; o; o >>= 1) s += __shfl_xor_sync(0xffffffffu, s, o);
    if ((tid & 31) == 0) ws[tid >> 5] = s;
    __syncthreads();
    if (tid == 0) stat[bh] = make_float2(M, 1.f / (ws[0] + ws[1]));
}

// ---------------- fold ----------------
#define FCH 16
#define NFCH (H_ / FCH)   // 64
__global__ __launch_bounds__(256)
void fold_kernel(const float* __restrict__ Wx, const float* __restrict__ Wl,
                 const float* __restrict__ pq, float* __restrict__ ufold)
{
    __shared__ float wl_s[NH_][FCH];
    const int n0 = blockIdx.x * FCH;
    const int b  = blockIdx.y;
    const int tid = threadIdx.x;

    if (tid < NH_ * FCH) {
        int h = tid >> 4, c = tid & 15;
        float v = Wl[h * H_ + n0 + c];
        if (pq) v *= pq[(size_t)b * H_ + n0 + c];
        wl_s[h][c] = v;
    }
    __syncthreads();

    const int i0 = tid * 4;
    float acc[NH_][4];
    #pragma unroll
    for (int h = 0; h < NH_; h++)
        #pragma unroll
        for (int e = 0; e < 4; e++) acc[h][e] = 0.f;

    #pragma unroll
    for (int nn = 0; nn < FCH; nn++) {
        float4 w4 = *(const float4*)(Wx + (size_t)(n0 + nn) * H_ + i0);
        #pragma unroll
        for (int h = 0; h < NH_; h++) {
            float wl = wl_s[h][nn];
            acc[h][0] = fmaf(wl, w4.x, acc[h][0]);
            acc[h][1] = fmaf(wl, w4.y, acc[h][1]);
            acc[h][2] = fmaf(wl, w4.z, acc[h][2]);
            acc[h][3] = fmaf(wl, w4.w, acc[h][3]);
        }
    }
    float* op = ufold + ((size_t)blockIdx.x * gridDim.y + b) * NH_ * H_;
    #pragma unroll
    for (int h = 0; h < NH_; h++)
        *(float4*)(op + h * H_ + i0) = *(float4*)acc[h];
}

__global__ __launch_bounds__(256)
void foldcvt_kernel(const float* __restrict__ in, __half* __restrict__ out,
                    int count, int sstride)
{
    int i = blockIdx.x * 256 + threadIdx.x;
    if (i >= count) return;
    float s = 0.f;
    #pragma unroll
    for (int n = 0; n < NFCH; n++) s += in[(size_t)n * sstride + i];
    out[i] = __float2half(s);
}

__global__ __launch_bounds__(256)
void sbias_kernel(const float* __restrict__ Wl, const float* __restrict__ bvec,
                  const float* __restrict__ badd, const float* __restrict__ pq,
                  float* __restrict__ sb)
{
    __shared__ float red[256];
    const int h = blockIdx.x, b = blockIdx.y, tid = threadIdx.x;
    float s = 0.f;
    for (int n = tid; n < H_; n += 256) {
        float v = Wl[h * H_ + n] * bvec[n];
        if (pq) v *= pq[(size_t)b * H_ + n];
        s += v;
    }
    red[tid] = s; __syncthreads();
    #pragma unroll
    for (int k2 = 128; k2; k2 >>= 1) {
        if (tid < k2) red[tid] += red[tid + k2];
        __syncthreads();
    }
    if (tid == 0) sb[b * NH_ + h] = red[0] + badd[h];
}

// ---------------- poolT ----------------
#define PJ 128
#define PT 1024
#define NTC 4
__global__ __launch_bounds__(256)
void poolT_kernel(const float* __restrict__ score, const float2* __restrict__ stat,
                  const __half* __restrict__ hs, float* __restrict__ ph)
{
    __shared__ float  w_s[NH_][128];
    __shared__ __half hs_s[128][PJ];
    __shared__ float  hmx[NH_], hinv[NH_];
    const int b = blockIdx.x, jc = blockIdx.y, tc = blockIdx.z;
    const int j0 = jc * PJ, t0 = tc * PT;
    const int tid = threadIdx.x;
    const int jj = (tid & 63) * 2;
    const int hg = tid >> 6;
    const uint32_t hsb = (uint32_t)__cvta_generic_to_shared(hs_s);

    if (tid < NH_) {
        float2 st = stat[b * NH_ + tid];
        hmx[tid] = st.x; hinv[tid] = st.y;
    }
    __syncthreads();

    float acc[4][2];
    #pragma unroll
    for (int e = 0; e < 4; e++) { acc[e][0] = 0.f; acc[e][1] = 0.f; }

    for (int tt = 0; tt < PT; tt += 128) {
        #pragma unroll
        for (int l = 0; l < 8; l++) {
            int idx = l * 256 + tid;
            int h = idx >> 7, t = idx & 127;
            float raw = score[((size_t)(b * NH_ + h)) * T_ + t0 + tt + t];
            w_s[h][t] = __expf(raw - hmx[h]) * hinv[h];
        }
        #pragma unroll
        for (int l = 0; l < 8; l++) {
            int c = l * 256 + tid;
            int row = c >> 4, ch = c & 15;
            cp16(hsb + (row * PJ + ch * 8) * 2,
                 hs + ((size_t)(b * T_ + t0 + tt + row)) * H_ + j0 + ch * 8);
        }
        cp_commit();
        cp_wait<0>();
        __syncthreads();

        for (int t = 0; t < 128; t++) {
            __half2 hv = *(__half2*)&hs_s[t][jj];
            float h0 = __low2float(hv), h1 = __high2float(hv);
            #pragma unroll
            for (int e = 0; e < 4; e++) {
                float wv = w_s[hg * 4 + e][t];
                acc[e][0] = fmaf(wv, h0, acc[e][0]);
                acc[e][1] = fmaf(wv, h1, acc[e][1]);
            }
        }
        __syncthreads();
    }
    #pragma unroll
    for (int e = 0; e < 4; e++) {
        size_t o = ((size_t)tc * B_ * NH_ + (size_t)b * NH_ + hg * 4 + e) * H_ + j0 + jj;
        ph[o]     = acc[e][0];
        ph[o + 1] = acc[e][1];
    }
}

// ---------------- recon ----------------
__global__ __launch_bounds__(256)
void recon_kernel(const float* __restrict__ ph, const float* __restrict__ Wx,
                  const float* __restrict__ bx, const float* __restrict__ pqin,
                  float* __restrict__ outp)
{
    __shared__ float phs[H_];
    const int b = blockIdx.x >> 4, h = blockIdx.x & 15;
    const int tid = threadIdx.x, wid = tid >> 5, lane = tid & 31;
    const size_t base = ((size_t)b * NH_ + h) * H_;
    const size_t tcs = (size_t)B_ * NH_ * H_;
    for (int i = tid; i < H_; i += 256)
        phs[i] = ph[base + i] + ph[tcs + base + i] +
                 ph[2 * tcs + base + i] + ph[3 * tcs + base + i];
    __syncthreads();

    #pragma unroll
    for (int r = 0; r < 8; r++) {
        int jg = h * 64 + wid * 8 + r;
        const float* wrow = Wx + (size_t)jg * H_;
        float s = 0.f;
        for (int i = lane; i < H_; i += 32) s = fmaf(wrow[i], phs[i], s);
        #pragma unroll
        for (int o = 16; o; o >>= 1) s += __shfl_xor_sync(0xffffffffu, s, o);
        if (lane == 0) {
            float v = s + bx[jg];
            size_t oo = (size_t)b * H_ + jg;
            if (pqin) v *= pqin[oo];
            outp[oo] = v;
        }
    }
}

// ---------------- fp32 -> fp16 convert ----------------
__global__ __launch_bounds__(256)
void cvt_kernel(const float* __restrict__ src, __half* __restrict__ dst, int n8)
{
    int i = blockIdx.x * 256 + threadIdx.x;
    if (i >= n8) return;
    float4 a = ((const float4*)src)[2 * i];
    float4 b = ((const float4*)src)[2 * i + 1];
    __half2 h0 = __floats2half2_rn(a.x, a.y), h1 = __floats2half2_rn(a.z, a.w);
    __half2 h2 = __floats2half2_rn(b.x, b.y), h3 = __floats2half2_rn(b.z, b.w);
    uint4 v;
    v.x = reinterpret_cast<uint32_t&>(h0);
    v.y = reinterpret_cast<uint32_t&>(h1);
    v.z = reinterpret_cast<uint32_t&>(h2);
    v.w = reinterpret_cast<uint32_t&>(h3);
    ((uint4*)dst)[i] = v;
}

// ---------------- wts[b,n,j] = fp16(Wt[n,j] * pk[b,j] * WTS_SCALE) ----------------
__global__ __launch_bounds__(256)
void scalew_kernel(const float* __restrict__ Wt, const float* __restrict__ pk,
                   __half* __restrict__ wts)
{
    size_t i = (size_t)blockIdx.x * 256 + threadIdx.x;
    size_t e = i * 4;
    int b = (int)(e >> 20);
    int r = (int)(e & (H_ * H_ - 1));
    int j = r & (H_ - 1);
    float4 w = *(const float4*)(Wt + r);
    float4 s = *(const float4*)(pk + (size_t)b * H_ + j);
    __half2 lo = __floats2half2_rn(w.x * s.x * WTS_SCALE, w.y * s.y * WTS_SCALE);
    __half2 hi = __floats2half2_rn(w.z * s.z * WTS_SCALE, w.w * s.w * WTS_SCALE);
    uint2 v;
    v.x = reinterpret_cast<uint32_t&>(lo);
    v.y = reinterpret_cast<uint32_t&>(hi);
    *(uint2*)(wts + e) = v;
}

// ---------------- launch ----------------
extern "C" void kernel_launch(void* const* d_in, const int* in_sizes, int n_in,
                              void* d_out, int out_size)
{
    const float* hs   = (const float*)d_in[0];
    const float* mask = (const float*)d_in[1];
    const float* Wq   = (const float*)d_in[2];
    const float* bq   = (const float*)d_in[3];
    const float* Wk   = (const float*)d_in[4];
    const float* bk   = (const float*)d_in[5];
    const float* Wql  = (const float*)d_in[6];
    const float* bql  = (const float*)d_in[7];
    const float* Wkl  = (const float*)d_in[8];
    const float* bkl  = (const float*)d_in[9];
    const float* Wt   = (const float*)d_in[10];
    const float* bt   = (const float*)d_in[11];
    float* out = (float*)d_out;

    __half *hsh, *qh, *wqh, *wts, *uqh, *ukh;
    float *ufoldq, *ufoldk, *score, *pmax, *psum, *ph, *pq, *pk, *sb;
    float2* stat;
    cudaGetSymbolAddress((void**)&hsh, g_hsh);
    cudaGetSymbolAddress((void**)&qh, g_qh);
    cudaGetSymbolAddress((void**)&wqh, g_wqh);
    cudaGetSymbolAddress((void**)&wts, g_wts);
    cudaGetSymbolAddress((void**)&uqh, g_uqh);
    cudaGetSymbolAddress((void**)&ukh, g_ukh);
    cudaGetSymbolAddress((void**)&ufoldq, g_ufold2);
    cudaGetSymbolAddress((void**)&ufoldk, g_ufoldk);
    cudaGetSymbolAddress((void**)&score, g_score);
    cudaGetSymbolAddress((void**)&pmax, g_pmax);
    cudaGetSymbolAddress((void**)&psum, g_psum);
    cudaGetSymbolAddress((void**)&ph, g_ph);
    cudaGetSymbolAddress((void**)&pq, g_pq);
    cudaGetSymbolAddress((void**)&pk, g_pk);
    cudaGetSymbolAddress((void**)&sb, g_sb);
    cudaGetSymbolAddress((void**)&stat, g_stat);

    cudaFuncSetAttribute(gemm_h<0>, cudaFuncAttributeMaxDynamicSharedMemorySize, SMEM_DYN);
    cudaFuncSetAttribute(gemm_h<1>, cudaFuncAttributeMaxDynamicSharedMemorySize, SMEM_DYN);
    cudaFuncSetAttribute(score_mma, cudaFuncAttributeMaxDynamicSharedMemorySize, S_SMEM);

    // 0. converts (main stream)
    {
        int n8 = (int)((size_t)MTOT * H_ / 8);
        cvt_kernel<<<(n8 + 255) / 256, 256>>>(hs, hsh, n8);
        int w8 = H_ * H_ / 8;
        cvt_kernel<<<(w8 + 255) / 256, 256>>>(Wq, wqh, w8);
    }

    // ---- fork: q-projection GEMM on side stream, pooling chain on main ----
    cudaEventRecord(g_sp.evFork, 0);
    cudaStreamWaitEvent(g_sp.side, g_sp.evFork, 0);

    // side: q = hs @ Wq^T + bq
    gemm_h<0><<<dim3(H_ / BN, MTOT / BM), 256, SMEM_DYN, g_sp.side>>>(
        hsh, wqh, bq, nullptr, qh, nullptr);
    cudaEventRecord(g_sp.evJoin, g_sp.side);

    // main: q-path (uses only hs + weights)
    fold_kernel<<<dim3(NFCH, 1), 256>>>(Wq, Wql, nullptr, ufoldq);
    foldcvt_kernel<<<(NH_ * H_) / 256, 256>>>(ufoldq, uqh, NH_ * H_, NH_ * H_);
    sbias_kernel<<<dim3(NH_, 1), 256>>>(Wql, bq, bql, nullptr, sb);
    score_mma<<<MTOT / 64, 128, S_SMEM>>>(hsh, uqh, sb, mask, score, pmax, psum, 0, 0);
    stats_comb<<<B_ * NH_, 64>>>(pmax, psum, stat);
    poolT_kernel<<<dim3(B_, H_ / PJ, NTC), 256>>>(score, stat, hsh, ph);
    recon_kernel<<<B_ * NH_, 256>>>(ph, Wq, bq, nullptr, pq);

    // main: k-path
    fold_kernel<<<dim3(NFCH, B_), 256>>>(Wk, Wkl, pq, ufoldk);
    foldcvt_kernel<<<(B_ * NH_ * H_) / 256, 256>>>(ufoldk, ukh, B_ * NH_ * H_, B_ * NH_ * H_);
    sbias_kernel<<<dim3(NH_, B_), 256>>>(Wkl, bk, bkl, pq, sb);
    score_mma<<<MTOT / 64, 128, S_SMEM>>>(hsh, ukh, sb, mask, score, pmax, psum, NH_ * H_, NH_);
    stats_comb<<<B_ * NH_, 64>>>(pmax, psum, stat);
    poolT_kernel<<<dim3(B_, H_ / PJ, NTC), 256>>>(score, stat, hsh, ph);
    recon_kernel<<<B_ * NH_, 256>>>(ph, Wk, bk, pq, pk);

    // main: wts[b] = fp16(Wt * pk[b] * 256)
    scalew_kernel<<<(B_ * H_ * H_ / 4 + 255) / 256, 256>>>(Wt, pk, wts);

    // ---- join: gemm<1> needs qh (side) + wts (main) ----
    cudaStreamWaitEvent(0, g_sp.evJoin, 0);
    gemm_h<1><<<dim3(H_ / BN, MTOT / BM), 256, SMEM_DYN>>>(
        qh, wts, bt, qh, nullptr, out);
}